// round 14
// baseline (speedup 1.0000x reference)
#include <cuda_runtime.h>
#include <cuda_fp16.h>
#include <cstdint>

#define NB    32
#define CIN   128
#define TLEN  4096
#define KBR   4
#define COUT  256
#define KS    7
#define PADL  3

// ---------------- device scratch ---------------------------------------------
__device__ float g_pooled16[16][NB * CIN];   // 16 deterministic t-slice partials
__device__ float g_alpha[NB * KBR];
__device__ unsigned int g_xt_ctr = 0;        // last-block-done counter (self-resetting)
// Weff fp16, layout [b][s][co][ci]  (ci contiguous)
__device__ __align__(16) __half g_wh[(size_t)NB * KS * COUT * CIN];
// x transposed fp16, layout [b][t][ci]  (ci contiguous)
__device__ __align__(16) __half g_xh[(size_t)NB * TLEN * CIN];

// ---------------- PTX helpers --------------------------------------------------
__device__ __forceinline__ uint32_t smem_to_u32(const void* p) {
    uint32_t a;
    asm("{ .reg .u64 t; cvta.to.shared.u64 t, %1; cvt.u32.u64 %0, t; }"
        : "=r"(a) : "l"(p));
    return a;
}
__device__ __forceinline__ void ldsm_x4(uint32_t& r0, uint32_t& r1,
                                        uint32_t& r2, uint32_t& r3, uint32_t addr) {
    asm volatile("ldmatrix.sync.aligned.m8n8.x4.shared.b16 {%0,%1,%2,%3}, [%4];"
                 : "=r"(r0), "=r"(r1), "=r"(r2), "=r"(r3) : "r"(addr));
}
__device__ __forceinline__ void mma_f16(float* d, const uint32_t* a,
                                        uint32_t b0, uint32_t b1) {
    asm volatile("mma.sync.aligned.m16n8k16.row.col.f32.f16.f16.f32 "
                 "{%0,%1,%2,%3}, {%4,%5,%6,%7}, {%8,%9}, {%0,%1,%2,%3};"
                 : "+f"(d[0]), "+f"(d[1]), "+f"(d[2]), "+f"(d[3])
                 : "r"(a[0]), "r"(a[1]), "r"(a[2]), "r"(a[3]), "r"(b0), "r"(b1));
}
#define CP_ASYNC16(dst, src) \
    asm volatile("cp.async.cg.shared.global [%0], [%1], 16;" :: "r"(dst), "l"(src))
#define CP_ASYNC16Z(dst, src, sz) \
    asm volatile("cp.async.cg.shared.global [%0], [%1], 16, %2;" \
                 :: "r"(dst), "l"(src), "r"(sz))
#define CP_COMMIT() asm volatile("cp.async.commit_group;" ::: "memory")
#define CP_WAIT0()  asm volatile("cp.async.wait_group 0;" ::: "memory")

// ---------------- conv smem layout ----------------------------------------------
#define A_TILE    32768
#define B_OFF     65536
#define B_TILE    34816
#define SMEM_TOTAL (B_OFF + B_TILE)   // 100352 -> occupancy 2

__device__ __forceinline__ uint32_t swz(int row, int c16) {    // 16 chunks/row
    return (uint32_t)(row * 256 + (((c16 & 8) | ((c16 ^ row) & 7)) << 4));
}

// ---------------- 1) fused x-transpose + fp16 + pool + routing softmax -----------
// grid (16 t-slices, 4 ci-chunks, NB), block 256: slab 32ci x 256t, 4 sub-tiles.
// The LAST block to finish (atomic counter) computes alpha for all batches.
__global__ __launch_bounds__(256) void xt2_kernel(const float* __restrict__ x,
                                                  const float* __restrict__ rw,
                                                  const float* __restrict__ rb) {
    __shared__ float tile[2][32][65];
    __shared__ unsigned int s_last;
    int b = blockIdx.z, ci0 = blockIdx.y * 32, tq = blockIdx.x;
    int tid = threadIdx.x;
    int rowr = tid >> 3, l8 = tid & 7;            // load: 8 threads per ci row
    int ts = tid >> 2, ci8 = (tid & 3) * 8;       // store: 4 threads per t row
    const float* src = x + ((size_t)(b * CIN + ci0 + rowr)) * TLEN
                         + tq * 256 + l8 * 8;
    float psum = 0.f;

    float4 pf[2][2];
    pf[0][0] = *reinterpret_cast<const float4*>(src);
    pf[0][1] = *reinterpret_cast<const float4*>(src + 4);
    pf[1][0] = *reinterpret_cast<const float4*>(src + 64);
    pf[1][1] = *reinterpret_cast<const float4*>(src + 68);

    #pragma unroll
    for (int sub = 0; sub < 4; sub++) {
        float4 v0 = pf[sub & 1][0];
        float4 v1 = pf[sub & 1][1];
        if (sub + 2 < 4) {
            pf[sub & 1][0] = *reinterpret_cast<const float4*>(src + (sub + 2) * 64);
            pf[sub & 1][1] = *reinterpret_cast<const float4*>(src + (sub + 2) * 64 + 4);
        }
        psum += (v0.x + v0.y) + (v0.z + v0.w) + (v1.x + v1.y) + (v1.z + v1.w);
        float* tr = &tile[sub & 1][rowr][l8 * 8];
        tr[0] = v0.x; tr[1] = v0.y; tr[2] = v0.z; tr[3] = v0.w;
        tr[4] = v1.x; tr[5] = v1.y; tr[6] = v1.z; tr[7] = v1.w;
        __syncthreads();
        __half2 h[4];
        #pragma unroll
        for (int i = 0; i < 4; i++)
            h[i] = __floats2half2_rn(tile[sub & 1][ci8 + 2 * i][ts],
                                     tile[sub & 1][ci8 + 2 * i + 1][ts]);
        int t = tq * 256 + sub * 64 + ts;
        *reinterpret_cast<uint4*>(g_xh + ((size_t)b * TLEN + t) * CIN + ci0 + ci8)
            = *reinterpret_cast<uint4*>(h);
    }
    #pragma unroll
    for (int o = 4; o; o >>= 1) psum += __shfl_down_sync(0xffffffffu, psum, o, 8);
    if (l8 == 0) g_pooled16[tq][b * CIN + ci0 + rowr] = psum * (1.0f / TLEN);

    // ---- last-block-done: compute routing softmax for all NB batches ------------
    __syncthreads();
    if (tid == 0) {
        __threadfence();
        unsigned int r = atomicAdd(&g_xt_ctr, 1u);
        s_last = (r == 16u * 4u * NB - 1u) ? 1u : 0u;
    }
    __syncthreads();
    if (s_last) {
        __threadfence();                         // acquire all pooled partials
        int w = tid >> 5, lane = tid & 31;       // warp w -> batches 4w..4w+3
        #pragma unroll
        for (int bb = 0; bb < 4; bb++) {
            int bt = w * 4 + bb;
            float p[4];
            #pragma unroll
            for (int c4 = 0; c4 < 4; c4++) {
                int ci = c4 * 32 + lane;
                float sum = 0.f;
                #pragma unroll
                for (int q = 0; q < 16; q++) sum += g_pooled16[q][bt * CIN + ci];
                p[c4] = sum;
            }
            float sc[KBR];
            #pragma unroll
            for (int k = 0; k < KBR; k++) {
                float v = 0.f;
                #pragma unroll
                for (int c4 = 0; c4 < 4; c4++)
                    v += p[c4] * rw[k * CIN + c4 * 32 + lane];
                #pragma unroll
                for (int o = 16; o; o >>= 1)
                    v += __shfl_down_sync(0xffffffffu, v, o);
                sc[k] = v;                        // valid on lane 0
            }
            if (lane == 0) {
                float m = -1e30f;
                #pragma unroll
                for (int k = 0; k < KBR; k++) {
                    sc[k] += rb[k];
                    m = fmaxf(m, sc[k]);
                }
                float den = 0.f;
                #pragma unroll
                for (int k = 0; k < KBR; k++) { sc[k] = __expf(sc[k] - m); den += sc[k]; }
                float inv = 1.0f / den;
                #pragma unroll
                for (int k = 0; k < KBR; k++) g_alpha[bt * KBR + k] = sc[k] * inv;
            }
        }
        __syncthreads();
        if (tid == 0) { __threadfence(); g_xt_ctr = 0; }   // replay-safe reset
    }
}

// ---------------- 2) Weff -> fp16: stage w[:,co] once, loop 16 batches -----------
__global__ __launch_bounds__(256) void weff2_kernel(const float* __restrict__ w) {
    __shared__ float wsm[KBR][CIN * KS];       // 14KB
    int co = blockIdx.x, bh = blockIdx.y;
    int tid = threadIdx.x;
    for (int i = tid; i < KBR * CIN * KS; i += 256) {
        int k = i / (CIN * KS), j = i - k * (CIN * KS);
        wsm[k][j] = w[((size_t)k * COUT + co) * (CIN * KS) + j];
    }
    __syncthreads();
    for (int b = bh * 16; b < bh * 16 + 16; b++) {
        float a0 = g_alpha[b * KBR + 0], a1 = g_alpha[b * KBR + 1];
        float a2 = g_alpha[b * KBR + 2], a3 = g_alpha[b * KBR + 3];
        for (int i = tid; i < 448; i += 256) {
            int s = i >> 6, c = i & 63;
            int j0 = (2 * c) * KS + s, j1 = j0 + KS;
            float v0 = a0 * wsm[0][j0] + a1 * wsm[1][j0]
                     + a2 * wsm[2][j0] + a3 * wsm[3][j0];
            float v1 = a0 * wsm[0][j1] + a1 * wsm[1][j1]
                     + a2 * wsm[2][j1] + a3 * wsm[3][j1];
            *reinterpret_cast<__half2*>(
                g_wh + (((size_t)b * KS + s) * COUT + co) * CIN + 2 * c)
                = __floats2half2_rn(v0, v1);
        }
    }
}

// ---------------- 3) routed conv via mma.sync fp16, software-pipelined -----------
__global__ __launch_bounds__(256, 2)
void conv_hmma_kernel(const float* __restrict__ bias, float* __restrict__ out) {
    extern __shared__ char smem[];
    uint32_t sbase = smem_to_u32(smem);
    int tid = threadIdx.x, wid = tid >> 5, lane = tid & 31;
    int t0  = blockIdx.x * 128;
    int co0 = blockIdx.y * 128;
    int b   = blockIdx.z;
    int co_w = (wid >> 1) * 32;      // warp co offset within tile
    int t_w  = (wid & 1) * 64;       // warp t offset within tile

    int a_row = lane & 15;           // A: row within 16
    int a_c   = lane >> 4;           // A: chunk select within k16
    int b_row = lane & 7;            // B: row within 8
    int b_g   = lane >> 3;           // B: chunk select 0..3 (covers 2 k16 steps)

    const __half* wh_b = g_wh + (((size_t)b * KS) * COUT + co0) * CIN;

    // ---- stage B via cp.async (zero-fill out-of-range): rows 0..135 -------------
    for (int idx = tid; idx < 136 * 16; idx += 256) {
        int row = idx >> 4, c16 = idx & 15;
        int tg  = t0 + row - PADL;
        uint32_t dst = sbase + B_OFF + swz(row, c16);
        const __half* src = g_xh + ((size_t)b * TLEN + tg) * CIN + c16 * 8;
        int sz = (tg >= 0 && tg < TLEN) ? 16 : 0;
        CP_ASYNC16Z(dst, src, sz);
    }

    // ---- A stage issue (cp.async, 8 chunks/thread): 128 co x 128 ci for tap s ---
    auto issueA = [&](int s, int buf) {
        #pragma unroll
        for (int i = 0; i < 8; i++) {
            int idx = tid + i * 256;             // 0..2047
            int row = idx >> 4, c16 = idx & 15;
            const __half* src = wh_b + ((size_t)s * COUT + row) * CIN + c16 * 8;
            CP_ASYNC16(sbase + (uint32_t)buf * A_TILE + swz(row, c16), src);
        }
        CP_COMMIT();
    };

    issueA(0, 0);    // commit covers B prologue + A stage 0

    float acc[2][8][4];
    #pragma unroll
    for (int m = 0; m < 2; m++)
        #pragma unroll
        for (int j = 0; j < 8; j++)
            #pragma unroll
            for (int q = 0; q < 4; q++) acc[m][j][q] = 0.f;

    uint32_t bb[2][4];               // B fragment double buffer
    const uint32_t bBase = sbase + B_OFF;

    for (int s = 0; s < KS; s++) {
        CP_WAIT0();
        __syncthreads();                 // stage s A + (s==0) B visible
        if (s + 1 < KS) issueA(s + 1, (s + 1) & 1);

        uint32_t aBuf = sbase + (uint32_t)(s & 1) * A_TILE;

        int rowb = t_w + s + b_row;
        uint32_t qb[4];
        #pragma unroll
        for (int q = 0; q < 4; q++) qb[q] = bBase + swz(rowb, q * 4 + b_g);
        uint32_t qb0n = bBase + swz(rowb + 1, b_g);

        if (s == 0)
            ldsm_x4(bb[0][0], bb[0][1], bb[0][2], bb[0][3], qb[0]);

        int pb = 0;
        #pragma unroll
        for (int q = 0; q < 4; q++) {
            uint32_t a[2][2][4];
            #pragma unroll
            for (int m = 0; m < 2; m++)
                #pragma unroll
                for (int kx = 0; kx < 2; kx++) {
                    uint32_t off = swz(co_w + m * 16 + a_row, (q * 2 + kx) * 2 + a_c);
                    ldsm_x4(a[m][kx][0], a[m][kx][1], a[m][kx][2], a[m][kx][3],
                            aBuf + off);
                }
            #pragma unroll
            for (int j = 0; j < 8; j++) {
                int np = pb ^ 1;
                if (j < 7) {
                    ldsm_x4(bb[np][0], bb[np][1], bb[np][2], bb[np][3],
                            qb[q] + (uint32_t)(j + 1) * 2048);
                } else if (q < 3) {
                    ldsm_x4(bb[np][0], bb[np][1], bb[np][2], bb[np][3], qb[q + 1]);
                } else if (s + 1 < KS) {
                    ldsm_x4(bb[np][0], bb[np][1], bb[np][2], bb[np][3], qb0n);
                }
                mma_f16(acc[0][j], a[0][0], bb[pb][0], bb[pb][1]);
                mma_f16(acc[1][j], a[1][0], bb[pb][0], bb[pb][1]);
                mma_f16(acc[0][j], a[0][1], bb[pb][2], bb[pb][3]);
                mma_f16(acc[1][j], a[1][1], bb[pb][2], bb[pb][3]);
                pb = np;
            }
        }
    }

    // ---- epilogue: bias_eff + direct stores (float2) ----------------------------
    float a0 = g_alpha[b * KBR + 0], a1 = g_alpha[b * KBR + 1];
    float a2 = g_alpha[b * KBR + 2], a3 = g_alpha[b * KBR + 3];
    int qr = lane >> 2, qc = (lane & 3) * 2;
    #pragma unroll
    for (int m = 0; m < 2; m++) {
        int coA = co0 + co_w + m * 16 + qr;
        int coB = coA + 8;
        float beA = a0 * bias[coA] + a1 * bias[COUT + coA]
                  + a2 * bias[2 * COUT + coA] + a3 * bias[3 * COUT + coA];
        float beB = a0 * bias[coB] + a1 * bias[COUT + coB]
                  + a2 * bias[2 * COUT + coB] + a3 * bias[3 * COUT + coB];
        float* pA = out + ((size_t)b * COUT + coA) * TLEN + t0 + t_w + qc;
        float* pB = out + ((size_t)b * COUT + coB) * TLEN + t0 + t_w + qc;
        #pragma unroll
        for (int j = 0; j < 8; j++) {
            float2 vA = make_float2(acc[m][j][0] + beA, acc[m][j][1] + beA);
            float2 vB = make_float2(acc[m][j][2] + beB, acc[m][j][3] + beB);
            *reinterpret_cast<float2*>(pA + j * 8) = vA;
            *reinterpret_cast<float2*>(pB + j * 8) = vB;
        }
    }
}

// ---------------- launch ----------------------------------------------------------
extern "C" void kernel_launch(void* const* d_in, const int* in_sizes, int n_in,
                              void* d_out, int out_size) {
    const float* x    = (const float*)d_in[0];   // [32,128,4096]
    const float* w    = (const float*)d_in[1];   // [4,256,128,7]
    const float* bias = (const float*)d_in[2];   // [4,256]
    const float* rw   = (const float*)d_in[3];   // [4,128]
    const float* rb   = (const float*)d_in[4];   // [4]
    float* out = (float*)d_out;                  // [32,256,4096]

    xt2_kernel  <<<dim3(16, CIN / 32, NB), 256>>>(x, rw, rb);
    weff2_kernel<<<dim3(COUT, 2), 256>>>(w);

    cudaFuncSetAttribute(conv_hmma_kernel,
                         cudaFuncAttributeMaxDynamicSharedMemorySize, SMEM_TOTAL);
    conv_hmma_kernel<<<dim3(TLEN / 128, COUT / 128, NB), 256, SMEM_TOTAL>>>(bias, out);
}

// round 15
// speedup vs baseline: 1.0564x; 1.0564x over previous
#include <cuda_runtime.h>
#include <cuda_fp16.h>
#include <cstdint>

#define NB    32
#define CIN   128
#define TLEN  4096
#define KBR   4
#define COUT  256
#define KS    7
#define PADL  3

// ---------------- device scratch ---------------------------------------------
__device__ float g_pooled16[16][NB * CIN];   // 16 deterministic t-slice partials
__device__ float g_alpha[NB * KBR];
// Weff fp16, layout [b][s][co][ci]  (ci contiguous)
__device__ __align__(16) __half g_wh[(size_t)NB * KS * COUT * CIN];
// x transposed fp16, layout [b][t][ci]  (ci contiguous)
__device__ __align__(16) __half g_xh[(size_t)NB * TLEN * CIN];

// ---------------- PTX helpers --------------------------------------------------
__device__ __forceinline__ uint32_t smem_to_u32(const void* p) {
    uint32_t a;
    asm("{ .reg .u64 t; cvta.to.shared.u64 t, %1; cvt.u32.u64 %0, t; }"
        : "=r"(a) : "l"(p));
    return a;
}
__device__ __forceinline__ void ldsm_x4(uint32_t& r0, uint32_t& r1,
                                        uint32_t& r2, uint32_t& r3, uint32_t addr) {
    asm volatile("ldmatrix.sync.aligned.m8n8.x4.shared.b16 {%0,%1,%2,%3}, [%4];"
                 : "=r"(r0), "=r"(r1), "=r"(r2), "=r"(r3) : "r"(addr));
}
__device__ __forceinline__ void mma_f16(float* d, const uint32_t* a,
                                        uint32_t b0, uint32_t b1) {
    asm volatile("mma.sync.aligned.m16n8k16.row.col.f32.f16.f16.f32 "
                 "{%0,%1,%2,%3}, {%4,%5,%6,%7}, {%8,%9}, {%0,%1,%2,%3};"
                 : "+f"(d[0]), "+f"(d[1]), "+f"(d[2]), "+f"(d[3])
                 : "r"(a[0]), "r"(a[1]), "r"(a[2]), "r"(a[3]), "r"(b0), "r"(b1));
}
#define CP_ASYNC16(dst, src) \
    asm volatile("cp.async.cg.shared.global [%0], [%1], 16;" :: "r"(dst), "l"(src))
#define CP_ASYNC16Z(dst, src, sz) \
    asm volatile("cp.async.cg.shared.global [%0], [%1], 16, %2;" \
                 :: "r"(dst), "l"(src), "r"(sz))
#define CP_COMMIT() asm volatile("cp.async.commit_group;" ::: "memory")
#define CP_WAIT0()  asm volatile("cp.async.wait_group 0;" ::: "memory")

// ---------------- conv smem layout ----------------------------------------------
#define A_TILE    32768
#define B_OFF     65536
#define B_TILE    34816
#define SMEM_TOTAL (B_OFF + B_TILE)   // 100352 -> occupancy 2

__device__ __forceinline__ uint32_t swz(int row, int c16) {    // 16 chunks/row
    return (uint32_t)(row * 256 + (((c16 & 8) | ((c16 ^ row) & 7)) << 4));
}

// ---------------- 1) fused x-transpose + fp16 + pooled partials -----------------
// grid (16 t-slices, 4 ci-chunks, NB), block 256: slab 32ci x 256t, 4 sub-tiles.
__global__ __launch_bounds__(256) void xt2_kernel(const float* __restrict__ x) {
    __shared__ float tile[2][32][65];
    int b = blockIdx.z, ci0 = blockIdx.y * 32, tq = blockIdx.x;
    int tid = threadIdx.x;
    int rowr = tid >> 3, l8 = tid & 7;            // load: 8 threads per ci row
    int ts = tid >> 2, ci8 = (tid & 3) * 8;       // store: 4 threads per t row
    const float* src = x + ((size_t)(b * CIN + ci0 + rowr)) * TLEN
                         + tq * 256 + l8 * 8;
    float psum = 0.f;

    float4 pf[2][2];
    pf[0][0] = *reinterpret_cast<const float4*>(src);
    pf[0][1] = *reinterpret_cast<const float4*>(src + 4);
    pf[1][0] = *reinterpret_cast<const float4*>(src + 64);
    pf[1][1] = *reinterpret_cast<const float4*>(src + 68);

    #pragma unroll
    for (int sub = 0; sub < 4; sub++) {
        float4 v0 = pf[sub & 1][0];
        float4 v1 = pf[sub & 1][1];
        if (sub + 2 < 4) {
            pf[sub & 1][0] = *reinterpret_cast<const float4*>(src + (sub + 2) * 64);
            pf[sub & 1][1] = *reinterpret_cast<const float4*>(src + (sub + 2) * 64 + 4);
        }
        psum += (v0.x + v0.y) + (v0.z + v0.w) + (v1.x + v1.y) + (v1.z + v1.w);
        float* tr = &tile[sub & 1][rowr][l8 * 8];
        tr[0] = v0.x; tr[1] = v0.y; tr[2] = v0.z; tr[3] = v0.w;
        tr[4] = v1.x; tr[5] = v1.y; tr[6] = v1.z; tr[7] = v1.w;
        __syncthreads();
        __half2 h[4];
        #pragma unroll
        for (int i = 0; i < 4; i++)
            h[i] = __floats2half2_rn(tile[sub & 1][ci8 + 2 * i][ts],
                                     tile[sub & 1][ci8 + 2 * i + 1][ts]);
        int t = tq * 256 + sub * 64 + ts;
        *reinterpret_cast<uint4*>(g_xh + ((size_t)b * TLEN + t) * CIN + ci0 + ci8)
            = *reinterpret_cast<uint4*>(h);
    }
    #pragma unroll
    for (int o = 4; o; o >>= 1) psum += __shfl_down_sync(0xffffffffu, psum, o, 8);
    if (l8 == 0) g_pooled16[tq][b * CIN + ci0 + rowr] = psum * (1.0f / TLEN);
}

// ---------------- 2) routing softmax ----------------------------------------------
__global__ void alpha_kernel(const float* __restrict__ rw,
                             const float* __restrict__ rb) {
    int b = blockIdx.x, tid = threadIdx.x;     // 128 threads
    int row = b * CIN + tid;
    float p = 0.f;
    #pragma unroll
    for (int q = 0; q < 16; q++) p += g_pooled16[q][row];
    __shared__ float part[KBR][4];
    int lane = tid & 31, wrp = tid >> 5;
    #pragma unroll
    for (int k = 0; k < KBR; k++) {
        float v = p * rw[k * CIN + tid];
        #pragma unroll
        for (int o = 16; o; o >>= 1) v += __shfl_down_sync(0xffffffffu, v, o);
        if (lane == 0) part[k][wrp] = v;
    }
    __syncthreads();
    if (tid == 0) {
        float sc[KBR], m = -1e30f;
        #pragma unroll
        for (int k = 0; k < KBR; k++) {
            sc[k] = part[k][0] + part[k][1] + part[k][2] + part[k][3] + rb[k];
            m = fmaxf(m, sc[k]);
        }
        float den = 0.f;
        #pragma unroll
        for (int k = 0; k < KBR; k++) { sc[k] = __expf(sc[k] - m); den += sc[k]; }
        float inv = 1.0f / den;
        #pragma unroll
        for (int k = 0; k < KBR; k++) g_alpha[b * KBR + k] = sc[k] * inv;
    }
}

// ---------------- 3) Weff -> fp16: stage w[:,co] once, loop 16 batches -----------
__global__ __launch_bounds__(256) void weff2_kernel(const float* __restrict__ w) {
    __shared__ float wsm[KBR][CIN * KS];       // 14KB
    int co = blockIdx.x, bh = blockIdx.y;
    int tid = threadIdx.x;
    for (int i = tid; i < KBR * CIN * KS; i += 256) {
        int k = i / (CIN * KS), j = i - k * (CIN * KS);
        wsm[k][j] = w[((size_t)k * COUT + co) * (CIN * KS) + j];
    }
    __syncthreads();
    for (int b = bh * 16; b < bh * 16 + 16; b++) {
        float a0 = g_alpha[b * KBR + 0], a1 = g_alpha[b * KBR + 1];
        float a2 = g_alpha[b * KBR + 2], a3 = g_alpha[b * KBR + 3];
        for (int i = tid; i < 448; i += 256) {
            int s = i >> 6, c = i & 63;
            int j0 = (2 * c) * KS + s, j1 = j0 + KS;
            float v0 = a0 * wsm[0][j0] + a1 * wsm[1][j0]
                     + a2 * wsm[2][j0] + a3 * wsm[3][j0];
            float v1 = a0 * wsm[0][j1] + a1 * wsm[1][j1]
                     + a2 * wsm[2][j1] + a3 * wsm[3][j1];
            *reinterpret_cast<__half2*>(
                g_wh + (((size_t)b * KS + s) * COUT + co) * CIN + 2 * c)
                = __floats2half2_rn(v0, v1);
        }
    }
}

// ---------------- 4) routed conv via mma.sync fp16, software-pipelined -----------
__global__ __launch_bounds__(256, 2)
void conv_hmma_kernel(const float* __restrict__ bias, float* __restrict__ out) {
    extern __shared__ char smem[];
    uint32_t sbase = smem_to_u32(smem);
    int tid = threadIdx.x, wid = tid >> 5, lane = tid & 31;
    int t0  = blockIdx.x * 128;
    int co0 = blockIdx.y * 128;
    int b   = blockIdx.z;
    int co_w = (wid >> 1) * 32;      // warp co offset within tile
    int t_w  = (wid & 1) * 64;       // warp t offset within tile

    int a_row = lane & 15;           // A: row within 16
    int a_c   = lane >> 4;           // A: chunk select within k16
    int b_row = lane & 7;            // B: row within 8
    int b_g   = lane >> 3;           // B: chunk select 0..3 (covers 2 k16 steps)

    const __half* wh_b = g_wh + (((size_t)b * KS) * COUT + co0) * CIN;

    // ---- stage B via cp.async (zero-fill out-of-range): rows 0..135 -------------
    for (int idx = tid; idx < 136 * 16; idx += 256) {
        int row = idx >> 4, c16 = idx & 15;
        int tg  = t0 + row - PADL;
        uint32_t dst = sbase + B_OFF + swz(row, c16);
        const __half* src = g_xh + ((size_t)b * TLEN + tg) * CIN + c16 * 8;
        int sz = (tg >= 0 && tg < TLEN) ? 16 : 0;
        CP_ASYNC16Z(dst, src, sz);
    }

    // ---- A stage issue (cp.async, 8 chunks/thread): 128 co x 128 ci for tap s ---
    auto issueA = [&](int s, int buf) {
        #pragma unroll
        for (int i = 0; i < 8; i++) {
            int idx = tid + i * 256;             // 0..2047
            int row = idx >> 4, c16 = idx & 15;
            const __half* src = wh_b + ((size_t)s * COUT + row) * CIN + c16 * 8;
            CP_ASYNC16(sbase + (uint32_t)buf * A_TILE + swz(row, c16), src);
        }
        CP_COMMIT();
    };

    issueA(0, 0);    // commit covers B prologue + A stage 0

    float acc[2][8][4];
    #pragma unroll
    for (int m = 0; m < 2; m++)
        #pragma unroll
        for (int j = 0; j < 8; j++)
            #pragma unroll
            for (int q = 0; q < 4; q++) acc[m][j][q] = 0.f;

    uint32_t bb[2][4];               // B fragment double buffer
    const uint32_t bBase = sbase + B_OFF;

    for (int s = 0; s < KS; s++) {
        CP_WAIT0();
        __syncthreads();                 // stage s A + (s==0) B visible
        if (s + 1 < KS) issueA(s + 1, (s + 1) & 1);

        uint32_t aBuf = sbase + (uint32_t)(s & 1) * A_TILE;

        int rowb = t_w + s + b_row;
        uint32_t qb[4];
        #pragma unroll
        for (int q = 0; q < 4; q++) qb[q] = bBase + swz(rowb, q * 4 + b_g);
        uint32_t qb0n = bBase + swz(rowb + 1, b_g);

        if (s == 0)
            ldsm_x4(bb[0][0], bb[0][1], bb[0][2], bb[0][3], qb[0]);

        int pb = 0;
        #pragma unroll
        for (int q = 0; q < 4; q++) {
            uint32_t a[2][2][4];
            #pragma unroll
            for (int m = 0; m < 2; m++)
                #pragma unroll
                for (int kx = 0; kx < 2; kx++) {
                    uint32_t off = swz(co_w + m * 16 + a_row, (q * 2 + kx) * 2 + a_c);
                    ldsm_x4(a[m][kx][0], a[m][kx][1], a[m][kx][2], a[m][kx][3],
                            aBuf + off);
                }
            #pragma unroll
            for (int j = 0; j < 8; j++) {
                int np = pb ^ 1;
                if (j < 7) {
                    ldsm_x4(bb[np][0], bb[np][1], bb[np][2], bb[np][3],
                            qb[q] + (uint32_t)(j + 1) * 2048);
                } else if (q < 3) {
                    ldsm_x4(bb[np][0], bb[np][1], bb[np][2], bb[np][3], qb[q + 1]);
                } else if (s + 1 < KS) {
                    ldsm_x4(bb[np][0], bb[np][1], bb[np][2], bb[np][3], qb0n);
                }
                mma_f16(acc[0][j], a[0][0], bb[pb][0], bb[pb][1]);
                mma_f16(acc[1][j], a[1][0], bb[pb][0], bb[pb][1]);
                mma_f16(acc[0][j], a[0][1], bb[pb][2], bb[pb][3]);
                mma_f16(acc[1][j], a[1][1], bb[pb][2], bb[pb][3]);
                pb = np;
            }
        }
    }

    // ---- epilogue: bias_eff + direct stores (float2) ----------------------------
    float a0 = g_alpha[b * KBR + 0], a1 = g_alpha[b * KBR + 1];
    float a2 = g_alpha[b * KBR + 2], a3 = g_alpha[b * KBR + 3];
    int qr = lane >> 2, qc = (lane & 3) * 2;
    #pragma unroll
    for (int m = 0; m < 2; m++) {
        int coA = co0 + co_w + m * 16 + qr;
        int coB = coA + 8;
        float beA = a0 * bias[coA] + a1 * bias[COUT + coA]
                  + a2 * bias[2 * COUT + coA] + a3 * bias[3 * COUT + coA];
        float beB = a0 * bias[coB] + a1 * bias[COUT + coB]
                  + a2 * bias[2 * COUT + coB] + a3 * bias[3 * COUT + coB];
        float* pA = out + ((size_t)b * COUT + coA) * TLEN + t0 + t_w + qc;
        float* pB = out + ((size_t)b * COUT + coB) * TLEN + t0 + t_w + qc;
        #pragma unroll
        for (int j = 0; j < 8; j++) {
            float2 vA = make_float2(acc[m][j][0] + beA, acc[m][j][1] + beA);
            float2 vB = make_float2(acc[m][j][2] + beB, acc[m][j][3] + beB);
            *reinterpret_cast<float2*>(pA + j * 8) = vA;
            *reinterpret_cast<float2*>(pB + j * 8) = vB;
        }
    }
}

// ---------------- launch ----------------------------------------------------------
extern "C" void kernel_launch(void* const* d_in, const int* in_sizes, int n_in,
                              void* d_out, int out_size) {
    const float* x    = (const float*)d_in[0];   // [32,128,4096]
    const float* w    = (const float*)d_in[1];   // [4,256,128,7]
    const float* bias = (const float*)d_in[2];   // [4,256]
    const float* rw   = (const float*)d_in[3];   // [4,128]
    const float* rb   = (const float*)d_in[4];   // [4]
    float* out = (float*)d_out;                  // [32,256,4096]

    xt2_kernel  <<<dim3(16, CIN / 32, NB), 256>>>(x);
    alpha_kernel<<<NB, 128>>>(rw, rb);
    weff2_kernel<<<dim3(COUT, 2), 256>>>(w);

    cudaFuncSetAttribute(conv_hmma_kernel,
                         cudaFuncAttributeMaxDynamicSharedMemorySize, SMEM_TOTAL);
    conv_hmma_kernel<<<dim3(TLEN / 128, COUT / 128, NB), 256, SMEM_TOTAL>>>(bias, out);
}